// round 4
// baseline (speedup 1.0000x reference)
#include <cuda_runtime.h>
#include <cuda_bf16.h>
#include <cstdint>

// ---------------------------------------------------------------------------
// out[n] = ||delta_n||^2  (exact fp32)  +  delta_n @ (S_inv - I) @ delta_n^T
// Correction GEMM in bf16 via mma.sync (HMMA) -- tcgen05 unavailable because
// the harness emits PTX at compute_103 (no 'a' feature set).
// ---------------------------------------------------------------------------

#define NROWS 65536
#define MTILE 128

// bf16 (S_inv - I), stored n-major [n][k], row = 1024B, SW-swizzled so that
// SMEM image == GMEM image (cp.async is a straight copy).
__device__ __align__(16) unsigned char g_Bt[512 * 1024];

#define SM_ROWSQ 0                    // 128 floats
#define SM_A     1024                 // 128 rows x 1024B (swizzled bf16 delta)
#define SM_B     (SM_A + 131072)      // 2 x 32KB double buffer
#define SM_TOTAL (SM_B + 2 * 32768)   // 197632 bytes

__device__ __forceinline__ uint32_t smem_u32(const void* p) {
    uint32_t a;
    asm("{ .reg .u64 t; cvta.to.shared.u64 t, %1; cvt.u32.u64 %0, t; }"
        : "=r"(a) : "l"(p));
    return a;
}

__device__ __forceinline__ void ldsm4(uint32_t* r, uint32_t addr) {
    asm volatile("ldmatrix.sync.aligned.m8n8.x4.shared.b16 {%0,%1,%2,%3}, [%4];"
                 : "=r"(r[0]), "=r"(r[1]), "=r"(r[2]), "=r"(r[3]) : "r"(addr));
}

__device__ __forceinline__ void mma16816(float* d, const uint32_t* a,
                                         const uint32_t* b, const float* c) {
    asm volatile(
        "mma.sync.aligned.m16n8k16.row.col.f32.bf16.bf16.f32 "
        "{%0,%1,%2,%3}, {%4,%5,%6,%7}, {%8,%9}, {%10,%11,%12,%13};"
        : "=f"(d[0]), "=f"(d[1]), "=f"(d[2]), "=f"(d[3])
        : "r"(a[0]), "r"(a[1]), "r"(a[2]), "r"(a[3]),
          "r"(b[0]), "r"(b[1]),
          "f"(c[0]), "f"(c[1]), "f"(c[2]), "f"(c[3]));
}

__device__ __forceinline__ void cp16(uint32_t dst, const void* src) {
    asm volatile("cp.async.cg.shared.global [%0], [%1], 16;"
                 :: "r"(dst), "l"(src));
}

// ---------------------------------------------------------------------------
// Prep: g_Bt[n][k] = bf16(S_inv[n][k] - (n==k)), swizzled.
// ---------------------------------------------------------------------------
__global__ void __launch_bounds__(256, 4)
prep_kernel(const float* __restrict__ S) {
    int p = blockIdx.x * 256 + threadIdx.x;   // 131072 threads, 2 elems each
    int n = p >> 8;
    int k = (p & 255) << 1;
    float v0 = S[n * 512 + k]     - (n == k     ? 1.0f : 0.0f);
    float v1 = S[n * 512 + k + 1] - (n == k + 1 ? 1.0f : 0.0f);
    uint32_t kb = (uint32_t)(k * 2);
    uint32_t off = (uint32_t)(n * 1024) + (kb ^ ((uint32_t)(n & 7) << 4));
    *(__nv_bfloat162*)(g_Bt + off) = __floats2bfloat162_rn(v0, v1);
}

// ---------------------------------------------------------------------------
extern __shared__ unsigned char smem[];

__global__ void __launch_bounds__(256, 1)
mahal_kernel(const float4* __restrict__ x4, const float4* __restrict__ f4,
             float* __restrict__ out) {
    const int tid  = threadIdx.x;
    const int wid  = tid >> 5;
    const int lane = tid & 31;
    const int m0   = blockIdx.x * MTILE;
    const uint32_t sbase = smem_u32(smem);
    float* rowsq = (float*)(smem + SM_ROWSQ);

    // --- prefetch B chunks 0,1 (overlap with phase 1 DRAM streaming) ---
    #pragma unroll
    for (int t = 0; t < 2; t++) {
        uint32_t dst = sbase + SM_B + t * 32768 + tid * 16;
        const unsigned char* src = g_Bt + t * 32768 + tid * 16;
        #pragma unroll
        for (int i = 0; i < 8; i++)
            cp16(dst + i * 4096, src + i * 4096);
        asm volatile("cp.async.commit_group;");
    }

    // --- phase 1: delta, exact rowsq, bf16 delta -> swizzled SMEM A ---
    {
        const int r0 = wid * 16;
        for (int rr = 0; rr < 16; rr++) {
            int r = r0 + rr;
            long gbase = (long)(m0 + r) * 128;
            float sq = 0.0f;
            #pragma unroll
            for (int q = 0; q < 4; q++) {
                int c4 = lane + q * 32;
                float4 xv = x4[gbase + c4];
                float4 fv = f4[gbase + c4];
                float d0 = xv.x - fv.x, d1 = xv.y - fv.y;
                float d2 = xv.z - fv.z, d3 = xv.w - fv.w;
                sq += d0 * d0 + d1 * d1 + d2 * d2 + d3 * d3;
                __nv_bfloat162 p0 = __floats2bfloat162_rn(d0, d1);
                __nv_bfloat162 p1 = __floats2bfloat162_rn(d2, d3);
                uint2 v;
                v.x = *reinterpret_cast<uint32_t*>(&p0);
                v.y = *reinterpret_cast<uint32_t*>(&p1);
                uint32_t kb = (uint32_t)(c4 * 8);
                uint32_t off = (uint32_t)(r * 1024)
                             + (kb ^ ((uint32_t)(r & 7) << 4));
                *(uint2*)(smem + SM_A + off) = v;
            }
            #pragma unroll
            for (int o = 16; o; o >>= 1)
                sq += __shfl_xor_sync(0xffffffffu, sq, o);
            if (lane == 0) rowsq[r] = sq;
        }
    }

    // --- phase 2: fused GEMM + row dot ---
    const int r0 = wid * 16;
    const int arow = r0 + (lane & 15);
    const uint32_t a_base = sbase + SM_A + arow * 1024;
    const uint32_t a_swz  = (uint32_t)(arow & 7) << 4;
    const uint32_t akoff  = (uint32_t)(lane >> 4) << 4;      // {0,16}

    const int bn1 = (lane & 7) + ((lane >> 4) << 3);         // n-row 0..15
    const uint32_t b_off1 = (uint32_t)(bn1 * 1024);
    const uint32_t b_off2 = (uint32_t)((bn1 + 16) * 1024);
    const uint32_t bkoff  = (uint32_t)((lane >> 3) & 1) << 4; // {0,16}
    const uint32_t bswz   = (uint32_t)(lane & 7) << 4;

    float z0 = 0.0f, z1 = 0.0f;

    for (int nc = 0; nc < 16; nc++) {
        asm volatile("cp.async.wait_group 1;" ::: "memory");
        __syncthreads();

        const uint32_t bbuf = sbase + SM_B + (nc & 1) * 32768;

        float acc0[4] = {0, 0, 0, 0};
        float acc1[4] = {0, 0, 0, 0};
        float acc2[4] = {0, 0, 0, 0};
        float acc3[4] = {0, 0, 0, 0};

        #pragma unroll 8
        for (int s = 0; s < 32; s++) {
            uint32_t kb = (uint32_t)(s * 32);
            uint32_t af[4], bf1[4], bf2[4];
            ldsm4(af,  a_base + ((kb + akoff) ^ a_swz));
            ldsm4(bf1, bbuf + b_off1 + ((kb + bkoff) ^ bswz));
            ldsm4(bf2, bbuf + b_off2 + ((kb + bkoff) ^ bswz));
            mma16816(acc0, af, bf1 + 0, acc0);
            mma16816(acc1, af, bf1 + 2, acc1);
            mma16816(acc2, af, bf2 + 0, acc2);
            mma16816(acc3, af, bf2 + 2, acc3);
        }

        // fused dot: chunk nc covers cols nc*32..+31 == ksteps 2nc, 2nc+1
        uint32_t da[4], db[4];
        ldsm4(da, a_base + (((uint32_t)(nc * 64)      + akoff) ^ a_swz));
        ldsm4(db, a_base + (((uint32_t)(nc * 64 + 32) + akoff) ^ a_swz));
        {
            float2 lo, hi;
            lo = __bfloat1622float2(*(__nv_bfloat162*)&da[0]);
            hi = __bfloat1622float2(*(__nv_bfloat162*)&da[1]);
            z0 += acc0[0] * lo.x + acc0[1] * lo.y;
            z1 += acc0[2] * hi.x + acc0[3] * hi.y;
            lo = __bfloat1622float2(*(__nv_bfloat162*)&da[2]);
            hi = __bfloat1622float2(*(__nv_bfloat162*)&da[3]);
            z0 += acc1[0] * lo.x + acc1[1] * lo.y;
            z1 += acc1[2] * hi.x + acc1[3] * hi.y;
            lo = __bfloat1622float2(*(__nv_bfloat162*)&db[0]);
            hi = __bfloat1622float2(*(__nv_bfloat162*)&db[1]);
            z0 += acc2[0] * lo.x + acc2[1] * lo.y;
            z1 += acc2[2] * hi.x + acc2[3] * hi.y;
            lo = __bfloat1622float2(*(__nv_bfloat162*)&db[2]);
            hi = __bfloat1622float2(*(__nv_bfloat162*)&db[3]);
            z0 += acc3[0] * lo.x + acc3[1] * lo.y;
            z1 += acc3[2] * hi.x + acc3[3] * hi.y;
        }

        __syncthreads();   // all warps done reading buffer (nc&1)

        if (nc + 2 < 16) {
            uint32_t dst = sbase + SM_B + (nc & 1) * 32768 + tid * 16;
            const unsigned char* src = g_Bt + (nc + 2) * 32768 + tid * 16;
            #pragma unroll
            for (int i = 0; i < 8; i++)
                cp16(dst + i * 4096, src + i * 4096);
        }
        asm volatile("cp.async.commit_group;");  // empty group ok: keeps count
    }

    // cross-lane reduce: lanes sharing (lane>>2) hold disjoint col pairs
    z0 += __shfl_xor_sync(0xffffffffu, z0, 1);
    z0 += __shfl_xor_sync(0xffffffffu, z0, 2);
    z1 += __shfl_xor_sync(0xffffffffu, z1, 1);
    z1 += __shfl_xor_sync(0xffffffffu, z1, 2);

    if ((lane & 3) == 0) {
        int row = r0 + (lane >> 2);
        out[m0 + row]     = rowsq[row]     + z0;
        out[m0 + row + 8] = rowsq[row + 8] + z1;
    }
}

// ---------------------------------------------------------------------------
extern "C" void kernel_launch(void* const* d_in, const int* in_sizes, int n_in,
                              void* d_out, int out_size) {
    const float* x  = (const float*)d_in[0];
    const float* xf = (const float*)d_in[1];
    const float* S  = (const float*)d_in[2];
    float* out = (float*)d_out;

    cudaFuncSetAttribute(mahal_kernel,
                         cudaFuncAttributeMaxDynamicSharedMemorySize, SM_TOTAL);

    prep_kernel<<<512, 256>>>(S);
    mahal_kernel<<<NROWS / MTILE, 256, SM_TOTAL>>>(
        (const float4*)x, (const float4*)xf, out);
}

// round 5
// speedup vs baseline: 1.1664x; 1.1664x over previous
#include <cuda_runtime.h>
#include <cuda_bf16.h>
#include <cstdint>

// ---------------------------------------------------------------------------
// out[n] = ||delta_n||^2 (exact fp32) + delta_n @ (S_inv - I) @ delta_n^T
// Correction GEMM in bf16 HMMA (mma.sync m16n8k16), warp tile 64Mx32N.
// ---------------------------------------------------------------------------

#define NROWS 65536
#define MTILE 128

// bf16 (S_inv - I), n-major [n][k], 1024B rows, 16B-unit swizzle (^ (n&7)<<4)
__device__ __align__(16) unsigned char g_Bt[512 * 1024];

#define SM_ROWSQ 0                     // 128 floats
#define SM_PART  512                   // 512 floats (4 nb-banks x 128 rows)
#define SM_A     4096                  // 128 x 1024B swizzled bf16 delta
#define SM_B     (SM_A + 131072)       // 2 x 32KB double buffer
#define SM_TOTAL (SM_B + 2 * 32768)    // 200704 bytes

__device__ __forceinline__ uint32_t smem_u32(const void* p) {
    uint32_t a;
    asm("{ .reg .u64 t; cvta.to.shared.u64 t, %1; cvt.u32.u64 %0, t; }"
        : "=r"(a) : "l"(p));
    return a;
}

__device__ __forceinline__ void ldsm4(uint32_t* r, uint32_t addr) {
    asm volatile("ldmatrix.sync.aligned.m8n8.x4.shared.b16 {%0,%1,%2,%3}, [%4];"
                 : "=r"(r[0]), "=r"(r[1]), "=r"(r[2]), "=r"(r[3]) : "r"(addr));
}

__device__ __forceinline__ void mma16816(float* d, const uint32_t* a,
                                         const uint32_t* b) {
    asm volatile(
        "mma.sync.aligned.m16n8k16.row.col.f32.bf16.bf16.f32 "
        "{%0,%1,%2,%3}, {%4,%5,%6,%7}, {%8,%9}, {%0,%1,%2,%3};"
        : "+f"(d[0]), "+f"(d[1]), "+f"(d[2]), "+f"(d[3])
        : "r"(a[0]), "r"(a[1]), "r"(a[2]), "r"(a[3]),
          "r"(b[0]), "r"(b[1]));
}

__device__ __forceinline__ void cp16(uint32_t dst, const void* src) {
    asm volatile("cp.async.cg.shared.global [%0], [%1], 16;"
                 :: "r"(dst), "l"(src));
}

// ---------------------------------------------------------------------------
__global__ void __launch_bounds__(256, 4)
prep_kernel(const float* __restrict__ S) {
    int p = blockIdx.x * 256 + threadIdx.x;
    int n = p >> 8;
    int k = (p & 255) << 1;
    float v0 = S[n * 512 + k]     - (n == k     ? 1.0f : 0.0f);
    float v1 = S[n * 512 + k + 1] - (n == k + 1 ? 1.0f : 0.0f);
    uint32_t kb = (uint32_t)(k * 2);
    uint32_t off = (uint32_t)(n * 1024) + (kb ^ ((uint32_t)(n & 7) << 4));
    *(__nv_bfloat162*)(g_Bt + off) = __floats2bfloat162_rn(v0, v1);
}

// ---------------------------------------------------------------------------
extern __shared__ unsigned char smem[];

__global__ void __launch_bounds__(256, 1)
mahal_kernel(const float4* __restrict__ x4, const float4* __restrict__ f4,
             float* __restrict__ out) {
    const int tid  = threadIdx.x;
    const int wid  = tid >> 5;
    const int lane = tid & 31;
    const int m0   = blockIdx.x * MTILE;
    const uint32_t sbase = smem_u32(smem);
    float* rowsq = (float*)(smem + SM_ROWSQ);
    float* part  = (float*)(smem + SM_PART);

    // --- prefetch B tiles 0,1 : tile t = (nc=t>>2, kc=t&3) = 128n x 256B ---
    #pragma unroll
    for (int t = 0; t < 2; t++) {
        uint32_t dst = sbase + SM_B + t * 32768;
        int nc = t >> 2, kc = t & 3;
        #pragma unroll
        for (int i = 0; i < 8; i++) {
            int e = tid + i * 256;            // 2048 16B units
            int n = (nc << 7) + (e >> 4), u = e & 15;
            cp16(dst + e * 16, g_Bt + n * 1024 + kc * 256 + u * 16);
        }
        asm volatile("cp.async.commit_group;");
    }

    // --- phase 1: delta, exact rowsq, bf16 delta -> swizzled SMEM A ---
    {
        const int r0 = wid * 16;
        for (int rr = 0; rr < 16; rr++) {
            int r = r0 + rr;
            long gbase = (long)(m0 + r) * 128;
            float sq = 0.0f;
            #pragma unroll
            for (int q = 0; q < 4; q++) {
                int c4 = lane + q * 32;
                float4 xv = x4[gbase + c4];
                float4 fv = f4[gbase + c4];
                float d0 = xv.x - fv.x, d1 = xv.y - fv.y;
                float d2 = xv.z - fv.z, d3 = xv.w - fv.w;
                sq += d0 * d0 + d1 * d1 + d2 * d2 + d3 * d3;
                __nv_bfloat162 p0 = __floats2bfloat162_rn(d0, d1);
                __nv_bfloat162 p1 = __floats2bfloat162_rn(d2, d3);
                uint2 v;
                v.x = *reinterpret_cast<uint32_t*>(&p0);
                v.y = *reinterpret_cast<uint32_t*>(&p1);
                uint32_t kb = (uint32_t)(c4 * 8);
                uint32_t off = (uint32_t)(r * 1024)
                             + (kb ^ ((uint32_t)(r & 7) << 4));
                *(uint2*)(smem + SM_A + off) = v;
            }
            #pragma unroll
            for (int o = 16; o; o >>= 1)
                sq += __shfl_xor_sync(0xffffffffu, sq, o);
            if (lane == 0) rowsq[r] = sq;
        }
        if (tid < 128) { part[tid] = 0.f; part[128+tid] = 0.f;
                         part[256+tid] = 0.f; part[384+tid] = 0.f; }
    }

    // --- phase 2: warp tile 64M x 32N ---
    const int mb = wid >> 2;               // 0/1 : rows mb*64..+64
    const int nb = wid & 3;                // 0..3: cols nb*32 within 128-chunk
    const uint32_t aswz  = (uint32_t)(lane & 7) << 4;
    const uint32_t akoff = (uint32_t)(lane >> 4) << 4;          // {0,16}
    const int bn1 = (lane & 7) + ((lane >> 4) << 3);            // n-row 0..15
    const uint32_t bkoff = (uint32_t)((lane >> 3) & 1) << 4;    // {0,16}

    uint32_t a_addr[4];
    #pragma unroll
    for (int sm = 0; sm < 4; sm++)
        a_addr[sm] = sbase + SM_A
                   + (uint32_t)((mb * 64 + sm * 16 + (lane & 15)) * 1024);
    uint32_t b_off[2];
    #pragma unroll
    for (int sn = 0; sn < 2; sn++)
        b_off[sn] = (uint32_t)((nb * 32 + sn * 16 + bn1) * 256);

    float acc[4][4][4];                    // [sm][n8][quad]
    float zl[4] = {0, 0, 0, 0}, zh[4] = {0, 0, 0, 0};

    for (int t = 0; t < 16; t++) {
        const int nc = t >> 2, kc = t & 3;
        asm volatile("cp.async.wait_group 1;" ::: "memory");
        __syncthreads();

        const uint32_t btile = sbase + SM_B + (t & 1) * 32768;

        if (kc == 0) {
            #pragma unroll
            for (int sm = 0; sm < 4; sm++)
                #pragma unroll
                for (int j = 0; j < 4; j++)
                    #pragma unroll
                    for (int q = 0; q < 4; q++)
                        acc[sm][j][q] = 0.0f;
        }

        #pragma unroll
        for (int s = 0; s < 8; s++) {
            uint32_t kb = (uint32_t)(kc * 256 + s * 32);
            uint32_t af[4][4], bf[8];
            #pragma unroll
            for (int sm = 0; sm < 4; sm++)
                ldsm4(af[sm], a_addr[sm] + ((kb + akoff) ^ aswz));
            #pragma unroll
            for (int sn = 0; sn < 2; sn++)
                ldsm4(bf + sn * 4,
                      btile + b_off[sn] + (((uint32_t)(s * 32) + bkoff) ^ aswz));
            #pragma unroll
            for (int sm = 0; sm < 4; sm++)
                #pragma unroll
                for (int j = 0; j < 4; j++)
                    mma16816(acc[sm][j], af[sm], bf + 2 * j);
        }

        if (kc == 3) {
            // fused dot for this 128-col n-chunk: cols nc*128 + nb*32 + sn*16
            #pragma unroll
            for (int sm = 0; sm < 4; sm++) {
                #pragma unroll
                for (int sn = 0; sn < 2; sn++) {
                    uint32_t nbyte = (uint32_t)(nc * 256 + nb * 64 + sn * 32);
                    uint32_t dd[4];
                    ldsm4(dd, a_addr[sm] + ((nbyte + akoff) ^ aswz));
                    float2 lo, hi;
                    lo = __bfloat1622float2(*(__nv_bfloat162*)&dd[0]);
                    hi = __bfloat1622float2(*(__nv_bfloat162*)&dd[1]);
                    zl[sm] += acc[sm][2*sn][0] * lo.x + acc[sm][2*sn][1] * lo.y;
                    zh[sm] += acc[sm][2*sn][2] * hi.x + acc[sm][2*sn][3] * hi.y;
                    lo = __bfloat1622float2(*(__nv_bfloat162*)&dd[2]);
                    hi = __bfloat1622float2(*(__nv_bfloat162*)&dd[3]);
                    zl[sm] += acc[sm][2*sn+1][0] * lo.x + acc[sm][2*sn+1][1] * lo.y;
                    zh[sm] += acc[sm][2*sn+1][2] * hi.x + acc[sm][2*sn+1][3] * hi.y;
                }
            }
        }

        __syncthreads();   // everyone done reading buffer (t&1)

        int tn = t + 2;
        if (tn < 16) {
            uint32_t dst = sbase + SM_B + (t & 1) * 32768;
            int ncn = tn >> 2, kcn = tn & 3;
            #pragma unroll
            for (int i = 0; i < 8; i++) {
                int e = tid + i * 256;
                int n = (ncn << 7) + (e >> 4), u = e & 15;
                cp16(dst + e * 16, g_Bt + n * 1024 + kcn * 256 + u * 16);
            }
        }
        asm volatile("cp.async.commit_group;");  // empty group keeps count
    }

    // --- reduce: lanes sharing (l>>2) hold disjoint col pairs ---
    #pragma unroll
    for (int sm = 0; sm < 4; sm++) {
        zl[sm] += __shfl_xor_sync(0xffffffffu, zl[sm], 1);
        zl[sm] += __shfl_xor_sync(0xffffffffu, zl[sm], 2);
        zh[sm] += __shfl_xor_sync(0xffffffffu, zh[sm], 1);
        zh[sm] += __shfl_xor_sync(0xffffffffu, zh[sm], 2);
    }
    if ((lane & 3) == 0) {
        #pragma unroll
        for (int sm = 0; sm < 4; sm++) {
            int row = mb * 64 + sm * 16 + (lane >> 2);
            part[nb * 128 + row]     = zl[sm];
            part[nb * 128 + row + 8] = zh[sm];
        }
    }
    __syncthreads();
    if (tid < 128)
        out[m0 + tid] = rowsq[tid] + part[tid] + part[128 + tid]
                      + part[256 + tid] + part[384 + tid];
}

// ---------------------------------------------------------------------------
extern "C" void kernel_launch(void* const* d_in, const int* in_sizes, int n_in,
                              void* d_out, int out_size) {
    const float* x  = (const float*)d_in[0];
    const float* xf = (const float*)d_in[1];
    const float* S  = (const float*)d_in[2];
    float* out = (float*)d_out;

    cudaFuncSetAttribute(mahal_kernel,
                         cudaFuncAttributeMaxDynamicSharedMemorySize, SM_TOTAL);

    prep_kernel<<<512, 256>>>(S);
    mahal_kernel<<<NROWS / MTILE, 256, SM_TOTAL>>>(
        (const float4*)x, (const float4*)xf, out);
}

// round 6
// speedup vs baseline: 1.2845x; 1.1012x over previous
#include <cuda_runtime.h>
#include <cuda_bf16.h>
#include <cuda_fp16.h>
#include <cstdint>

// ---------------------------------------------------------------------------
// out[n] = ||delta_n||^2 (exact fp32) + (1/512) * delta @ (512*(S_inv-I)) @ delta^T
// Correction GEMM in fp8 e4m3 via mma.sync m16n8k32. 2 CTAs/SM.
// ---------------------------------------------------------------------------

#define NROWS 65536
#define MTILE 128

// fp8 512*(S_inv - I), 16 tiles of 16KB: tile t=(n>>7)*4+(k>>7),
// in-tile: nn*128 + (kk ^ ((nn&7)<<4))  -- SMEM image == GMEM image.
__device__ __align__(16) unsigned char g_B[512 * 512];

#define SM_ROWSQ 0                     // 128 floats
#define SM_PART  512                   // 512 floats
#define SM_A     4096                  // 128 rows x 512B fp8 delta (swizzled)
#define SM_B     (SM_A + 65536)        // 2 x 16KB double buffer
#define SM_TOTAL (SM_B + 2 * 16384)    // 102400 bytes

__device__ __forceinline__ uint32_t smem_u32(const void* p) {
    uint32_t a;
    asm("{ .reg .u64 t; cvta.to.shared.u64 t, %1; cvt.u32.u64 %0, t; }"
        : "=r"(a) : "l"(p));
    return a;
}

__device__ __forceinline__ void ldsm4(uint32_t* r, uint32_t addr) {
    asm volatile("ldmatrix.sync.aligned.m8n8.x4.shared.b16 {%0,%1,%2,%3}, [%4];"
                 : "=r"(r[0]), "=r"(r[1]), "=r"(r[2]), "=r"(r[3]) : "r"(addr));
}

__device__ __forceinline__ void mma16832(float* d, const uint32_t* a,
                                         const uint32_t* b) {
    asm volatile(
        "mma.sync.aligned.m16n8k32.row.col.f32.e4m3.e4m3.f32 "
        "{%0,%1,%2,%3}, {%4,%5,%6,%7}, {%8,%9}, {%0,%1,%2,%3};"
        : "+f"(d[0]), "+f"(d[1]), "+f"(d[2]), "+f"(d[3])
        : "r"(a[0]), "r"(a[1]), "r"(a[2]), "r"(a[3]),
          "r"(b[0]), "r"(b[1]));
}

__device__ __forceinline__ void cp16(uint32_t dst, const void* src) {
    asm volatile("cp.async.cg.shared.global [%0], [%1], 16;"
                 :: "r"(dst), "l"(src));
}

__device__ __forceinline__ uint16_t f2e4m3x2(float hi, float lo) {
    uint16_t r;
    asm("cvt.rn.satfinite.e4m3x2.f32 %0, %1, %2;" : "=h"(r) : "f"(hi), "f"(lo));
    return r;
}

__device__ __forceinline__ float2 e4m3x2_2f(uint16_t v) {
    uint32_t h;
    asm("cvt.rn.f16x2.e4m3x2 %0, %1;" : "=r"(h) : "h"(v));
    return __half22float2(*reinterpret_cast<__half2*>(&h));
}

// ---------------------------------------------------------------------------
__global__ void __launch_bounds__(256, 4)
prep_kernel(const float* __restrict__ S) {
    int p = blockIdx.x * 256 + threadIdx.x;   // 131072 threads, 2 elems each
    int n = p >> 8;
    int k = (p & 255) << 1;
    float v0 = (S[n * 512 + k]     - (n == k     ? 1.0f : 0.0f)) * 512.0f;
    float v1 = (S[n * 512 + k + 1] - (n == k + 1 ? 1.0f : 0.0f)) * 512.0f;
    int t = (n >> 7) * 4 + (k >> 7);
    uint32_t nn = (uint32_t)(n & 127), kk = (uint32_t)(k & 127);
    uint32_t off = (uint32_t)(t * 16384) + nn * 128 + (kk ^ ((nn & 7) << 4));
    *(uint16_t*)(g_B + off) = f2e4m3x2(v1, v0);
}

// ---------------------------------------------------------------------------
extern __shared__ unsigned char smem[];

__global__ void __launch_bounds__(256, 2)
mahal_kernel(const float4* __restrict__ x4, const float4* __restrict__ f4,
             float* __restrict__ out) {
    const int tid  = threadIdx.x;
    const int wid  = tid >> 5;
    const int lane = tid & 31;
    const int m0   = blockIdx.x * MTILE;
    const uint32_t sbase = smem_u32(smem);
    float* rowsq = (float*)(smem + SM_ROWSQ);
    float* part  = (float*)(smem + SM_PART);

    // --- prefetch B tiles 0,1 (16KB each = 4 cp16/thread) ---
    #pragma unroll
    for (int t = 0; t < 2; t++) {
        uint32_t dst = sbase + SM_B + t * 16384;
        const unsigned char* src = g_B + t * 16384;
        #pragma unroll
        for (int i = 0; i < 4; i++) {
            int e = tid + i * 256;
            cp16(dst + e * 16, src + e * 16);
        }
        asm volatile("cp.async.commit_group;");
    }

    // --- phase 1: delta, exact fp32 rowsq, fp8 delta -> swizzled SMEM A ---
    {
        const int r0 = wid * 16;
        for (int rr = 0; rr < 16; rr++) {
            int r = r0 + rr;
            long gbase = (long)(m0 + r) * 128;
            float sq = 0.0f;
            uint32_t rswz = (uint32_t)(r & 7) << 4;
            #pragma unroll
            for (int q = 0; q < 4; q++) {
                int c4 = lane + q * 32;
                float4 xv = x4[gbase + c4];
                float4 fv = f4[gbase + c4];
                float d0 = xv.x - fv.x, d1 = xv.y - fv.y;
                float d2 = xv.z - fv.z, d3 = xv.w - fv.w;
                sq += d0 * d0 + d1 * d1 + d2 * d2 + d3 * d3;
                uint32_t v = (uint32_t)f2e4m3x2(d1, d0)
                           | ((uint32_t)f2e4m3x2(d3, d2) << 16);
                uint32_t off = (uint32_t)(r * 512)
                             + (((uint32_t)(c4 * 4)) ^ rswz);
                *(uint32_t*)(smem + SM_A + off) = v;
            }
            #pragma unroll
            for (int o = 16; o; o >>= 1)
                sq += __shfl_xor_sync(0xffffffffu, sq, o);
            if (lane == 0) rowsq[r] = sq;
        }
        if (tid < 128) { part[tid] = 0.f; part[128+tid] = 0.f;
                         part[256+tid] = 0.f; part[384+tid] = 0.f; }
    }

    // --- phase 2: warp tile 64M x 32N, fp8 k32 steps ---
    const int mb = wid >> 2;                 // rows mb*64..+63
    const int nb = wid & 3;                  // cols nb*32 within 128-chunk
    const uint32_t aswz  = (uint32_t)(lane & 7) << 4;
    const uint32_t akoff = (uint32_t)(lane >> 4) << 4;         // {0,16}
    const int bn1 = (lane & 7) + ((lane >> 4) << 3);
    const uint32_t bkoff = (uint32_t)((lane >> 3) & 1) << 4;   // {0,16}

    uint32_t a_addr[4];
    #pragma unroll
    for (int sm = 0; sm < 4; sm++)
        a_addr[sm] = sbase + SM_A
                   + (uint32_t)((mb * 64 + sm * 16 + (lane & 15)) * 512);
    uint32_t b_off[2];
    #pragma unroll
    for (int sn = 0; sn < 2; sn++)
        b_off[sn] = (uint32_t)((nb * 32 + sn * 16 + bn1) * 128);

    float acc[4][4][4];                      // [sm][n8][quad]
    float zl[4] = {0, 0, 0, 0}, zh[4] = {0, 0, 0, 0};

    for (int t = 0; t < 16; t++) {
        const int nc = t >> 2, kc = t & 3;
        asm volatile("cp.async.wait_group 1;" ::: "memory");
        __syncthreads();

        const uint32_t btile = sbase + SM_B + (t & 1) * 16384;

        if (kc == 0) {
            #pragma unroll
            for (int sm = 0; sm < 4; sm++)
                #pragma unroll
                for (int j = 0; j < 4; j++)
                    #pragma unroll
                    for (int q = 0; q < 4; q++)
                        acc[sm][j][q] = 0.0f;
        }

        #pragma unroll
        for (int s = 0; s < 4; s++) {
            uint32_t af[4][4], bf[2][4];
            uint32_t akb = (uint32_t)(kc * 128 + s * 32);
            #pragma unroll
            for (int sm = 0; sm < 4; sm++)
                ldsm4(af[sm], a_addr[sm] + ((akb + akoff) ^ aswz));
            #pragma unroll
            for (int sn = 0; sn < 2; sn++)
                ldsm4(bf[sn],
                      btile + b_off[sn] + (((uint32_t)(s * 32) + bkoff) ^ aswz));
            #pragma unroll
            for (int sm = 0; sm < 4; sm++)
                #pragma unroll
                for (int j = 0; j < 4; j++)
                    mma16832(acc[sm][j], af[sm], bf[j >> 1] + (j & 1) * 2);
        }

        if (kc == 3) {
            // fused dot over this 128-col n-chunk
            #pragma unroll
            for (int sm = 0; sm < 4; sm++) {
                int row_lo = mb * 64 + sm * 16 + (lane >> 2);
                uint32_t base_lo = sbase + SM_A + (uint32_t)(row_lo * 512);
                uint32_t swz = (uint32_t)(row_lo & 7) << 4;  // same for +8
                #pragma unroll
                for (int j = 0; j < 4; j++) {
                    uint32_t kbyte = (uint32_t)(nc * 128 + nb * 32 + j * 8
                                                + (lane & 3) * 2);
                    uint32_t off = kbyte ^ swz;
                    uint16_t vlo = *(const uint16_t*)(smem + SM_A
                                       + (base_lo - sbase - SM_A) + off);
                    uint16_t vhi = *(const uint16_t*)(smem + SM_A
                                       + (base_lo - sbase - SM_A) + 8 * 512 + off);
                    float2 flo = e4m3x2_2f(vlo);
                    float2 fhi = e4m3x2_2f(vhi);
                    zl[sm] += flo.x * acc[sm][j][0] + flo.y * acc[sm][j][1];
                    zh[sm] += fhi.x * acc[sm][j][2] + fhi.y * acc[sm][j][3];
                }
            }
        }

        __syncthreads();

        int tn = t + 2;
        if (tn < 16) {
            uint32_t dst = sbase + SM_B + (t & 1) * 16384;
            const unsigned char* src = g_B + tn * 16384;
            #pragma unroll
            for (int i = 0; i < 4; i++) {
                int e = tid + i * 256;
                cp16(dst + e * 16, src + e * 16);
            }
        }
        asm volatile("cp.async.commit_group;");
    }

    // --- reduce over the 4 lanes of each quad-row group ---
    #pragma unroll
    for (int sm = 0; sm < 4; sm++) {
        zl[sm] += __shfl_xor_sync(0xffffffffu, zl[sm], 1);
        zl[sm] += __shfl_xor_sync(0xffffffffu, zl[sm], 2);
        zh[sm] += __shfl_xor_sync(0xffffffffu, zh[sm], 1);
        zh[sm] += __shfl_xor_sync(0xffffffffu, zh[sm], 2);
    }
    if ((lane & 3) == 0) {
        #pragma unroll
        for (int sm = 0; sm < 4; sm++) {
            int row = mb * 64 + sm * 16 + (lane >> 2);
            part[nb * 128 + row]     = zl[sm];
            part[nb * 128 + row + 8] = zh[sm];
        }
    }
    __syncthreads();
    if (tid < 128)
        out[m0 + tid] = rowsq[tid]
                      + (part[tid] + part[128 + tid]
                         + part[256 + tid] + part[384 + tid]) * (1.0f / 512.0f);
}

// ---------------------------------------------------------------------------
extern "C" void kernel_launch(void* const* d_in, const int* in_sizes, int n_in,
                              void* d_out, int out_size) {
    const float* x  = (const float*)d_in[0];
    const float* xf = (const float*)d_in[1];
    const float* S  = (const float*)d_in[2];
    float* out = (float*)d_out;

    cudaFuncSetAttribute(mahal_kernel,
                         cudaFuncAttributeMaxDynamicSharedMemorySize, SM_TOTAL);

    prep_kernel<<<512, 256>>>(S);
    mahal_kernel<<<NROWS / MTILE, 256, SM_TOTAL>>>(
        (const float4*)x, (const float4*)xf, out);
}

// round 9
// speedup vs baseline: 1.5545x; 1.2102x over previous
#include <cuda_runtime.h>
#include <cuda_bf16.h>
#include <cuda_fp16.h>
#include <cstdint>

// ---------------------------------------------------------------------------
// out[n] = ||delta_n||^2 (exact fp32) + (1/512)*delta @ (512*(S_inv-I)) @ delta^T
// S_inv symmetric  =>  only lower-triangle 128x128 blocks computed,
// off-diagonal block dots weighted by 2.  fp8 e4m3 mma.sync m16n8k32.
// ---------------------------------------------------------------------------

#define NROWS 65536
#define MTILE 128

// fp8 512*(S_inv - I), 16 tiles of 16KB: tile t=(n>>7)*4+(k>>7),
// in-tile: nn*128 + (kk ^ ((nn&7)<<4))  -- SMEM image == GMEM image.
__device__ __align__(16) unsigned char g_B[512 * 512];

#define SM_ROWSQ 0                     // 128 floats
#define SM_PART  512                   // 512 floats
#define SM_A     4096                  // 128 rows x 512B fp8 delta (swizzled)
#define SM_B     (SM_A + 65536)        // 2 x 16KB double buffer
#define SM_TOTAL (SM_B + 2 * 16384)    // 102400 bytes

__device__ __forceinline__ uint32_t smem_u32(const void* p) {
    uint32_t a;
    asm("{ .reg .u64 t; cvta.to.shared.u64 t, %1; cvt.u32.u64 %0, t; }"
        : "=r"(a) : "l"(p));
    return a;
}

__device__ __forceinline__ void ldsm4(uint32_t* r, uint32_t addr) {
    asm volatile("ldmatrix.sync.aligned.m8n8.x4.shared.b16 {%0,%1,%2,%3}, [%4];"
                 : "=r"(r[0]), "=r"(r[1]), "=r"(r[2]), "=r"(r[3]) : "r"(addr));
}

__device__ __forceinline__ void mma16832(float* d, const uint32_t* a,
                                         const uint32_t* b) {
    asm volatile(
        "mma.sync.aligned.m16n8k32.row.col.f32.e4m3.e4m3.f32 "
        "{%0,%1,%2,%3}, {%4,%5,%6,%7}, {%8,%9}, {%0,%1,%2,%3};"
        : "+f"(d[0]), "+f"(d[1]), "+f"(d[2]), "+f"(d[3])
        : "r"(a[0]), "r"(a[1]), "r"(a[2]), "r"(a[3]),
          "r"(b[0]), "r"(b[1]));
}

__device__ __forceinline__ void cp16(uint32_t dst, const void* src) {
    asm volatile("cp.async.cg.shared.global [%0], [%1], 16;"
                 :: "r"(dst), "l"(src));
}

__device__ __forceinline__ uint16_t f2e4m3x2(float hi, float lo) {
    uint16_t r;
    asm("cvt.rn.satfinite.e4m3x2.f32 %0, %1, %2;" : "=h"(r) : "f"(hi), "f"(lo));
    return r;
}

__device__ __forceinline__ float2 e4m3x2_2f(uint16_t v) {
    uint32_t h;
    asm("cvt.rn.f16x2.e4m3x2 %0, %1;" : "=r"(h) : "h"(v));
    return __half22float2(*reinterpret_cast<__half2*>(&h));
}

// ---------------------------------------------------------------------------
__global__ void __launch_bounds__(256, 4)
prep_kernel(const float* __restrict__ S) {
    int p = blockIdx.x * 256 + threadIdx.x;   // 131072 threads, 2 elems each
    int n = p >> 8;
    int k = (p & 255) << 1;
    float v0 = (S[n * 512 + k]     - (n == k     ? 1.0f : 0.0f)) * 512.0f;
    float v1 = (S[n * 512 + k + 1] - (n == k + 1 ? 1.0f : 0.0f)) * 512.0f;
    int t = (n >> 7) * 4 + (k >> 7);
    uint32_t nn = (uint32_t)(n & 127), kk = (uint32_t)(k & 127);
    uint32_t off = (uint32_t)(t * 16384) + nn * 128 + (kk ^ ((nn & 7) << 4));
    *(uint16_t*)(g_B + off) = f2e4m3x2(v1, v0);
}

// ---------------------------------------------------------------------------
extern __shared__ unsigned char smem[];

__global__ void __launch_bounds__(256, 2)
mahal_kernel(const float4* __restrict__ x4, const float4* __restrict__ f4,
             float* __restrict__ out) {
    const int tid  = threadIdx.x;
    const int wid  = tid >> 5;
    const int lane = tid & 31;
    const int m0   = blockIdx.x * MTILE;
    const uint32_t sbase = smem_u32(smem);
    float* rowsq = (float*)(smem + SM_ROWSQ);
    float* part  = (float*)(smem + SM_PART);

    // --- prefetch first two triangle tiles: (0,0)->t0, (1,0)->t4 ---
    {
        uint32_t dst = sbase + SM_B;
        #pragma unroll
        for (int i = 0; i < 4; i++) {
            int e = tid + i * 256;
            cp16(dst + e * 16, g_B + e * 16);
        }
        asm volatile("cp.async.commit_group;");
        dst += 16384;
        #pragma unroll
        for (int i = 0; i < 4; i++) {
            int e = tid + i * 256;
            cp16(dst + e * 16, g_B + 4 * 16384 + e * 16);
        }
        asm volatile("cp.async.commit_group;");
    }

    // --- phase 1: delta, exact fp32 rowsq, fp8 delta -> swizzled SMEM A ---
    {
        const int r0 = wid * 16;
        for (int rr = 0; rr < 16; rr++) {
            int r = r0 + rr;
            long gbase = (long)(m0 + r) * 128;
            float sq = 0.0f;
            uint32_t rswz = (uint32_t)(r & 7) << 4;
            #pragma unroll
            for (int q = 0; q < 4; q++) {
                int c4 = lane + q * 32;
                float4 xv = x4[gbase + c4];
                float4 fv = f4[gbase + c4];
                float d0 = xv.x - fv.x, d1 = xv.y - fv.y;
                float d2 = xv.z - fv.z, d3 = xv.w - fv.w;
                sq += d0 * d0 + d1 * d1 + d2 * d2 + d3 * d3;
                uint32_t v = (uint32_t)f2e4m3x2(d1, d0)
                           | ((uint32_t)f2e4m3x2(d3, d2) << 16);
                uint32_t off = (uint32_t)(r * 512)
                             + (((uint32_t)(c4 * 4)) ^ rswz);
                *(uint32_t*)(smem + SM_A + off) = v;
            }
            #pragma unroll
            for (int o = 16; o; o >>= 1)
                sq += __shfl_xor_sync(0xffffffffu, sq, o);
            if (lane == 0) rowsq[r] = sq;
        }
    }

    // --- phase 2: lower-triangle tiles, warp tile 64M x 32N ---
    const int mb = wid >> 2;
    const int nb = wid & 3;
    const uint32_t aswz  = (uint32_t)(lane & 7) << 4;
    const uint32_t akoff = (uint32_t)(lane >> 4) << 4;
    const int bn1 = (lane & 7) + ((lane >> 4) << 3);
    const uint32_t bkoff = (uint32_t)((lane >> 3) & 1) << 4;

    uint32_t a_addr[4];
    #pragma unroll
    for (int sm = 0; sm < 4; sm++)
        a_addr[sm] = sbase + SM_A
                   + (uint32_t)((mb * 64 + sm * 16 + (lane & 15)) * 512);
    uint32_t b_off[2];
    #pragma unroll
    for (int sn = 0; sn < 2; sn++)
        b_off[sn] = (uint32_t)((nb * 32 + sn * 16 + bn1) * 128);

    // dot-side precomputed addressing
    const int rq = lane >> 2;                      // quad row 0..7
    uint32_t d_base[4];
    uint32_t d_swz;
    {
        int row_lo = mb * 64 + (lane >> 2);
        d_swz = (uint32_t)(row_lo & 7) << 4;
        #pragma unroll
        for (int sm = 0; sm < 4; sm++)
            d_base[sm] = (uint32_t)((mb * 64 + sm * 16 + rq) * 512);
    }

    float acc[4][4][4];
    float zl[4] = {0, 0, 0, 0}, zh[4] = {0, 0, 0, 0};

    int p = 0;             // linear tile counter (buffer parity)
    int nc2 = 1, kc2 = 1;  // (nc,kc) of tile p+2

    for (int nc = 0; nc < 4; nc++) {
        for (int kc = 0; kc <= nc; kc++) {
            asm volatile("cp.async.wait_group 1;" ::: "memory");
            __syncthreads();

            const uint32_t btile = sbase + SM_B + (p & 1) * 16384;

            #pragma unroll
            for (int sm = 0; sm < 4; sm++)
                #pragma unroll
                for (int j = 0; j < 4; j++)
                    #pragma unroll
                    for (int q = 0; q < 4; q++)
                        acc[sm][j][q] = 0.0f;

            #pragma unroll
            for (int s = 0; s < 4; s++) {
                uint32_t af[4][4], bf[2][4];
                uint32_t akb = (uint32_t)(kc * 128 + s * 32);
                #pragma unroll
                for (int sm = 0; sm < 4; sm++)
                    ldsm4(af[sm], a_addr[sm] + ((akb + akoff) ^ aswz));
                #pragma unroll
                for (int sn = 0; sn < 2; sn++)
                    ldsm4(bf[sn], btile + b_off[sn]
                          + (((uint32_t)(s * 32) + bkoff) ^ aswz));
                #pragma unroll
                for (int sm = 0; sm < 4; sm++)
                    #pragma unroll
                    for (int j = 0; j < 4; j++)
                        mma16832(acc[sm][j], af[sm], bf[j >> 1] + (j & 1) * 2);
            }

            // fused dot over this tile's 128 e-cols (warp's 32), weight 1 / 2
            {
                const float w = (nc == kc) ? 1.0f : 2.0f;
                #pragma unroll
                for (int sm = 0; sm < 4; sm++) {
                    #pragma unroll
                    for (int j = 0; j < 4; j++) {
                        uint32_t kbyte = (uint32_t)(nc * 128 + nb * 32 + j * 8
                                                    + (lane & 3) * 2);
                        uint32_t off = kbyte ^ d_swz;
                        uint16_t vlo = *(const uint16_t*)(smem + SM_A
                                           + d_base[sm] + off);
                        uint16_t vhi = *(const uint16_t*)(smem + SM_A
                                           + d_base[sm] + 8 * 512 + off);
                        float2 flo = e4m3x2_2f(vlo);
                        float2 fhi = e4m3x2_2f(vhi);
                        zl[sm] += w * (flo.x * acc[sm][j][0]
                                     + flo.y * acc[sm][j][1]);
                        zh[sm] += w * (fhi.x * acc[sm][j][2]
                                     + fhi.y * acc[sm][j][3]);
                    }
                }
            }

            __syncthreads();

            if (nc2 < 4) {
                uint32_t dst = sbase + SM_B + (p & 1) * 16384;
                const unsigned char* src = g_B + (nc2 * 4 + kc2) * 16384;
                #pragma unroll
                for (int i = 0; i < 4; i++) {
                    int e = tid + i * 256;
                    cp16(dst + e * 16, src + e * 16);
                }
            }
            asm volatile("cp.async.commit_group;");

            kc2++;
            if (kc2 > nc2) { nc2++; kc2 = 0; }
            p++;
        }
    }

    // --- reduce over the 4 lanes of each quad-row group ---
    #pragma unroll
    for (int sm = 0; sm < 4; sm++) {
        zl[sm] += __shfl_xor_sync(0xffffffffu, zl[sm], 1);
        zl[sm] += __shfl_xor_sync(0xffffffffu, zl[sm], 2);
        zh[sm] += __shfl_xor_sync(0xffffffffu, zh[sm], 1);
        zh[sm] += __shfl_xor_sync(0xffffffffu, zh[sm], 2);
    }
    if ((lane & 3) == 0) {
        #pragma unroll
        for (int sm = 0; sm < 4; sm++) {
            int row = mb * 64 + sm * 16 + (lane >> 2);
            part[nb * 128 + row]     = zl[sm];
            part[nb * 128 + row + 8] = zh[sm];
        }
    }
    __syncthreads();
    if (tid < 128)
        out[m0 + tid] = rowsq[tid]
                      + (part[tid] + part[128 + tid]
                         + part[256 + tid] + part[384 + tid]) * (1.0f / 512.0f);
}

// ---------------------------------------------------------------------------
extern "C" void kernel_launch(void* const* d_in, const int* in_sizes, int n_in,
                              void* d_out, int out_size) {
    const float* x  = (const float*)d_in[0];
    const float* xf = (const float*)d_in[1];
    const float* S  = (const float*)d_in[2];
    float* out = (float*)d_out;

    cudaFuncSetAttribute(mahal_kernel,
                         cudaFuncAttributeMaxDynamicSharedMemorySize, SM_TOTAL);

    prep_kernel<<<512, 256>>>(S);
    mahal_kernel<<<NROWS / MTILE, 256, SM_TOTAL>>>(
        (const float4*)x, (const float4*)xf, out);
}